// round 2
// baseline (speedup 1.0000x reference)
#include <cuda_runtime.h>
#include <math.h>

#define BATCH 8
#define SS 1048576              // 128*128*64
#define NTOT (BATCH * SS)       // 8388608 per component

// ---------------- scratch (device globals; no allocation) ----------------
__device__ float g_s_re[NTOT];
__device__ float g_s_im[NTOT];
__device__ float g_u_re[NTOT];
__device__ float g_u_im[NTOT];
__device__ float g_l_re[NTOT];
__device__ float g_l_im[NTOT];
__device__ float g_p_re[2097152];   // split-K partials (NC*B*d*d, both modes == 2M)
__device__ float g_p_im[2097152];
__device__ float g_sc_re[131072];   // score  (B*d*d max = 8*128*128)
__device__ float g_sc_im[131072];
__device__ float g_m_re[131072];    // routing matrix
__device__ float g_m_im[131072];

// ---------------- complex GEMM: C[b] = A(b?) * U[b],  (M=K=d, N=rest) -----
#define BM 64
#define BN 64
#define BKT 16
#define SPAD 68                 // padded smem row (16B-aligned, conflict-light)

__global__ __launch_bounds__(256, 2)
void cgemm_nn(const float* __restrict__ Are, const float* __restrict__ Aim, int strideA,
              const float* __restrict__ Ure, const float* __restrict__ Uim,
              float* __restrict__ Cre, float* __restrict__ Cim,
              int d, int rest)
{
    __shared__ float As_re[BKT][SPAD], As_im[BKT][SPAD];
    __shared__ float Bs_re[BKT][SPAD], Bs_im[BKT][SPAD];

    const int b  = blockIdx.z;
    const int m0 = blockIdx.y * BM;
    const int n0 = blockIdx.x * BN;

    const float* are = Are + (size_t)b * strideA;
    const float* aim = Aim + (size_t)b * strideA;
    const float* ure = Ure + (size_t)b * d * rest;
    const float* uim = Uim + (size_t)b * d * rest;
    float*       cre = Cre + (size_t)b * d * rest;
    float*       cim = Cim + (size_t)b * d * rest;

    const int tid = threadIdx.x;
    const int tn  = tid & 15;
    const int tm  = tid >> 4;

    const int arow = tid >> 2;          // 0..63
    const int ac4  = (tid & 3) * 4;     // 0,4,8,12
    const int ukr  = tid >> 4;          // 0..15
    const int un4  = (tid & 15) * 4;    // 0..60

    float cr[4][4], ci_[4][4];
#pragma unroll
    for (int i = 0; i < 4; i++)
#pragma unroll
        for (int j = 0; j < 4; j++) { cr[i][j] = 0.f; ci_[i][j] = 0.f; }

    for (int kk = 0; kk < d; kk += BKT) {
        float4 a4r = *(const float4*)(are + (size_t)(m0 + arow) * d + kk + ac4);
        float4 a4i = *(const float4*)(aim + (size_t)(m0 + arow) * d + kk + ac4);
        As_re[ac4 + 0][arow] = a4r.x; As_re[ac4 + 1][arow] = a4r.y;
        As_re[ac4 + 2][arow] = a4r.z; As_re[ac4 + 3][arow] = a4r.w;
        As_im[ac4 + 0][arow] = a4i.x; As_im[ac4 + 1][arow] = a4i.y;
        As_im[ac4 + 2][arow] = a4i.z; As_im[ac4 + 3][arow] = a4i.w;

        float4 u4r = *(const float4*)(ure + (size_t)(kk + ukr) * rest + n0 + un4);
        float4 u4i = *(const float4*)(uim + (size_t)(kk + ukr) * rest + n0 + un4);
        *(float4*)&Bs_re[ukr][un4] = u4r;
        *(float4*)&Bs_im[ukr][un4] = u4i;

        __syncthreads();
#pragma unroll
        for (int k = 0; k < BKT; k++) {
            float4 arv = *(const float4*)&As_re[k][tm * 4];
            float4 aiv = *(const float4*)&As_im[k][tm * 4];
            float4 brv = *(const float4*)&Bs_re[k][tn * 4];
            float4 biv = *(const float4*)&Bs_im[k][tn * 4];
            float ar_[4] = {arv.x, arv.y, arv.z, arv.w};
            float ai2[4] = {aiv.x, aiv.y, aiv.z, aiv.w};
            float br_[4] = {brv.x, brv.y, brv.z, brv.w};
            float bi2[4] = {biv.x, biv.y, biv.z, biv.w};
#pragma unroll
            for (int i = 0; i < 4; i++)
#pragma unroll
                for (int j = 0; j < 4; j++) {
                    cr[i][j]  = fmaf(ar_[i],  br_[j], cr[i][j]);
                    cr[i][j]  = fmaf(-ai2[i], bi2[j], cr[i][j]);
                    ci_[i][j] = fmaf(ar_[i],  bi2[j], ci_[i][j]);
                    ci_[i][j] = fmaf(ai2[i],  br_[j], ci_[i][j]);
                }
        }
        __syncthreads();
    }

#pragma unroll
    for (int i = 0; i < 4; i++) {
        int m = m0 + tm * 4 + i;
        float4 orr = {cr[i][0], cr[i][1], cr[i][2], cr[i][3]};
        float4 oii = {ci_[i][0], ci_[i][1], ci_[i][2], ci_[i][3]};
        *(float4*)(cre + (size_t)m * rest + n0 + tn * 4) = orr;
        *(float4*)(cim + (size_t)m * rest + n0 + tn * 4) = oii;
    }
}

// ---------- complex GEMM NT split-K: P[c][b] += L[b] * U[b]^T -------------
// L: (B, d, K) row-major, U: (B, d, K) row-major (so this is A*B^T), K split into chunks
__global__ __launch_bounds__(256, 2)
void cgemm_nt(const float* __restrict__ Lre, const float* __restrict__ Lim,
              const float* __restrict__ Ure, const float* __restrict__ Uim,
              float* __restrict__ Pre, float* __restrict__ Pim,
              int d, int K, int KC)
{
    __shared__ float As_re[BKT][SPAD], As_im[BKT][SPAD];
    __shared__ float Bs_re[BKT][SPAD], Bs_im[BKT][SPAD];

    const int bz    = blockIdx.z;
    const int b     = bz & 7;
    const int chunk = bz >> 3;
    const int m0    = blockIdx.y * BM;
    const int n0    = blockIdx.x * BN;

    const float* lre = Lre + (size_t)b * d * K;
    const float* lim = Lim + (size_t)b * d * K;
    const float* ure = Ure + (size_t)b * d * K;
    const float* uim = Uim + (size_t)b * d * K;

    const int tid = threadIdx.x;
    const int tn  = tid & 15;
    const int tm  = tid >> 4;
    const int arow = tid >> 2;
    const int ac4  = (tid & 3) * 4;

    float cr[4][4], ci_[4][4];
#pragma unroll
    for (int i = 0; i < 4; i++)
#pragma unroll
        for (int j = 0; j < 4; j++) { cr[i][j] = 0.f; ci_[i][j] = 0.f; }

    const int kbeg = chunk * KC;
    for (int kk = kbeg; kk < kbeg + KC; kk += BKT) {
        float4 a4r = *(const float4*)(lre + (size_t)(m0 + arow) * K + kk + ac4);
        float4 a4i = *(const float4*)(lim + (size_t)(m0 + arow) * K + kk + ac4);
        As_re[ac4 + 0][arow] = a4r.x; As_re[ac4 + 1][arow] = a4r.y;
        As_re[ac4 + 2][arow] = a4r.z; As_re[ac4 + 3][arow] = a4r.w;
        As_im[ac4 + 0][arow] = a4i.x; As_im[ac4 + 1][arow] = a4i.y;
        As_im[ac4 + 2][arow] = a4i.z; As_im[ac4 + 3][arow] = a4i.w;

        float4 b4r = *(const float4*)(ure + (size_t)(n0 + arow) * K + kk + ac4);
        float4 b4i = *(const float4*)(uim + (size_t)(n0 + arow) * K + kk + ac4);
        Bs_re[ac4 + 0][arow] = b4r.x; Bs_re[ac4 + 1][arow] = b4r.y;
        Bs_re[ac4 + 2][arow] = b4r.z; Bs_re[ac4 + 3][arow] = b4r.w;
        Bs_im[ac4 + 0][arow] = b4i.x; Bs_im[ac4 + 1][arow] = b4i.y;
        Bs_im[ac4 + 2][arow] = b4i.z; Bs_im[ac4 + 3][arow] = b4i.w;

        __syncthreads();
#pragma unroll
        for (int k = 0; k < BKT; k++) {
            float4 arv = *(const float4*)&As_re[k][tm * 4];
            float4 aiv = *(const float4*)&As_im[k][tm * 4];
            float4 brv = *(const float4*)&Bs_re[k][tn * 4];
            float4 biv = *(const float4*)&Bs_im[k][tn * 4];
            float ar_[4] = {arv.x, arv.y, arv.z, arv.w};
            float ai2[4] = {aiv.x, aiv.y, aiv.z, aiv.w};
            float br_[4] = {brv.x, brv.y, brv.z, brv.w};
            float bi2[4] = {biv.x, biv.y, biv.z, biv.w};
#pragma unroll
            for (int i = 0; i < 4; i++)
#pragma unroll
                for (int j = 0; j < 4; j++) {
                    cr[i][j]  = fmaf(ar_[i],  br_[j], cr[i][j]);
                    cr[i][j]  = fmaf(-ai2[i], bi2[j], cr[i][j]);
                    ci_[i][j] = fmaf(ar_[i],  bi2[j], ci_[i][j]);
                    ci_[i][j] = fmaf(ai2[i],  br_[j], ci_[i][j]);
                }
        }
        __syncthreads();
    }

    size_t off = (size_t)(chunk * BATCH + b) * d * d;
#pragma unroll
    for (int i = 0; i < 4; i++) {
        int m = m0 + tm * 4 + i;
        float4 orr = {cr[i][0], cr[i][1], cr[i][2], cr[i][3]};
        float4 oii = {ci_[i][0], ci_[i][1], ci_[i][2], ci_[i][3]};
        *(float4*)(Pre + off + (size_t)m * d + n0 + tn * 4) = orr;
        *(float4*)(Pim + off + (size_t)m * d + n0 + tn * 4) = oii;
    }
}

// ---------------- deterministic split-K reduction -------------------------
__global__ void reduce_parts(const float* __restrict__ Pre, const float* __restrict__ Pim,
                             float* __restrict__ Sre, float* __restrict__ Sim,
                             int n, int nchunks)
{
    int i = blockIdx.x * 256 + threadIdx.x;
    if (i >= n) return;
    float ar = 0.f, ai = 0.f;
    for (int c = 0; c < nchunks; c++) {
        ar += Pre[(size_t)c * n + i];
        ai += Pim[(size_t)c * n + i];
    }
    Sre[i] = ar; Sim[i] = ai;
}

// ---------------- softmax(|s|/scale) * phase ------------------------------
__global__ void softmax_phase(const float* __restrict__ Sre, const float* __restrict__ Sim,
                              float* __restrict__ Mre, float* __restrict__ Mim,
                              int d, const float* __restrict__ logtau, float sfac)
{
    const int row = blockIdx.x;
    const int j   = threadIdx.x;
    const float sr = Sre[(size_t)row * d + j];
    const float si = Sim[(size_t)row * d + j];
    const float mag = sqrtf(sr * sr + si * si);

    const float tau   = fmaxf(expf(logtau[0]), 1e-8f);
    const float scale = tau * sfac;
    const float logit = mag / scale;

    __shared__ float wred[4];
    __shared__ float wsum[4];
    const int warp = j >> 5, lane = j & 31, nw = d >> 5;

    float v = logit;
#pragma unroll
    for (int o = 16; o > 0; o >>= 1) v = fmaxf(v, __shfl_xor_sync(0xffffffffu, v, o));
    if (lane == 0) wred[warp] = v;
    __syncthreads();
    float mx = wred[0];
    for (int w = 1; w < nw; w++) mx = fmaxf(mx, wred[w]);

    const float e = expf(logit - mx);
    float s_ = e;
#pragma unroll
    for (int o = 16; o > 0; o >>= 1) s_ += __shfl_xor_sync(0xffffffffu, s_, o);
    if (lane == 0) wsum[warp] = s_;
    __syncthreads();
    float tot = 0.f;
    for (int w = 0; w < nw; w++) tot += wsum[w];

    const float routing = e / tot;
    float pr, pi;
    if (mag > 1e-8f) { pr = sr / mag; pi = si / mag; }
    else             { pr = 1.f;      pi = 0.f; }
    Mre[(size_t)row * d + j] = routing * pr;
    Mim[(size_t)row * d + j] = routing * pi;
}

// ---------------- mode-1 permute: swap the two 128-axes (k innermost) ----
__global__ void perm_swap01(const float* __restrict__ sre, const float* __restrict__ sim,
                            float* __restrict__ dre, float* __restrict__ dim_)
{
    int idx = blockIdx.x * 256 + threadIdx.x;      // < 8388608
    int k = idx & 63;
    int q = (idx >> 6) & 127;
    int p = (idx >> 13) & 127;
    int b = idx >> 20;
    int src = (b << 20) | (q << 13) | (p << 6) | k;
    dre[idx] = sre[src];
    dim_[idx] = sim[src];
}

// ---------------- batched 2D transpose: dst[b][c][r] = src[b][r][c] -------
__global__ void perm_transpose(const float* __restrict__ sre, const float* __restrict__ sim,
                               float* __restrict__ dre, float* __restrict__ dim_,
                               int R, int C)
{
    __shared__ float tre[32][33], tim[32][33];
    const int b  = blockIdx.z;
    const int r0 = blockIdx.y * 32;
    const int c0 = blockIdx.x * 32;
    const float* sr_ = sre + (size_t)b * R * C;
    const float* si_ = sim + (size_t)b * R * C;
    float*       dr_ = dre + (size_t)b * R * C;
    float*       di_ = dim_ + (size_t)b * R * C;
    const int x = threadIdx.x, y = threadIdx.y;    // 32 x 8
#pragma unroll
    for (int i = y; i < 32; i += 8) {
        tre[i][x] = sr_[(size_t)(r0 + i) * C + c0 + x];
        tim[i][x] = si_[(size_t)(r0 + i) * C + c0 + x];
    }
    __syncthreads();
#pragma unroll
    for (int i = y; i < 32; i += 8) {
        dr_[(size_t)(c0 + i) * R + r0 + x] = tre[x][i];
        di_[(size_t)(c0 + i) * R + r0 + x] = tim[x][i];
    }
}

// --------------------------------------------------------------------------
extern "C" void kernel_launch(void* const* d_in, const int* in_sizes, int n_in,
                              void* d_out, int out_size)
{
    (void)in_sizes; (void)n_in; (void)out_size;
    const float* xre  = (const float*)d_in[0];
    const float* xim  = (const float*)d_in[1];
    const float* w0re = (const float*)d_in[2];
    const float* w0im = (const float*)d_in[3];
    const float* w1re = (const float*)d_in[4];
    const float* w1im = (const float*)d_in[5];
    const float* w2re = (const float*)d_in[6];
    const float* w2im = (const float*)d_in[7];
    const float* ltau = (const float*)d_in[8];
    float* out_re = (float*)d_out;
    float* out_im = out_re + (size_t)NTOT;

    float *s_re, *s_im, *u_re, *u_im, *l_re, *l_im, *p_re, *p_im, *sc_re, *sc_im, *m_re, *m_im;
    cudaGetSymbolAddress((void**)&s_re,  g_s_re);
    cudaGetSymbolAddress((void**)&s_im,  g_s_im);
    cudaGetSymbolAddress((void**)&u_re,  g_u_re);
    cudaGetSymbolAddress((void**)&u_im,  g_u_im);
    cudaGetSymbolAddress((void**)&l_re,  g_l_re);
    cudaGetSymbolAddress((void**)&l_im,  g_l_im);
    cudaGetSymbolAddress((void**)&p_re,  g_p_re);
    cudaGetSymbolAddress((void**)&p_im,  g_p_im);
    cudaGetSymbolAddress((void**)&sc_re, g_sc_re);
    cudaGetSymbolAddress((void**)&sc_im, g_sc_im);
    cudaGetSymbolAddress((void**)&m_re,  g_m_re);
    cudaGetSymbolAddress((void**)&m_im,  g_m_im);

    // ---------------- Mode 0: d=128, rest=8192 (unfold = identity) --------
    {
        const int d = 128, rest = 8192;
        dim3 g1(rest / BN, d / BM, BATCH);
        cgemm_nn<<<g1, 256>>>(w0re, w0im, 0, xre, xim, l_re, l_im, d, rest);

        const int NC = 16, KC = rest / NC;        // 512
        dim3 g2(d / BN, d / BM, BATCH * NC);
        cgemm_nt<<<g2, 256>>>(l_re, l_im, xre, xim, p_re, p_im, d, rest, KC);

        const int n = BATCH * d * d;
        reduce_parts<<<(n + 255) / 256, 256>>>(p_re, p_im, sc_re, sc_im, n, NC);
        softmax_phase<<<BATCH * d, d>>>(sc_re, sc_im, m_re, m_im, d, ltau,
                                        sqrtf((float)SS / (float)d));
        cgemm_nn<<<g1, 256>>>(m_re, m_im, d * d, xre, xim, s_re, s_im, d, rest);
    }

    // ---------------- Mode 1: d=128, rest=8192 ----------------------------
    {
        const int d = 128, rest = 8192;
        perm_swap01<<<NTOT / 256, 256>>>(s_re, s_im, u_re, u_im);

        dim3 g1(rest / BN, d / BM, BATCH);
        cgemm_nn<<<g1, 256>>>(w1re, w1im, 0, u_re, u_im, l_re, l_im, d, rest);

        const int NC = 16, KC = rest / NC;
        dim3 g2(d / BN, d / BM, BATCH * NC);
        cgemm_nt<<<g2, 256>>>(l_re, l_im, u_re, u_im, p_re, p_im, d, rest, KC);

        const int n = BATCH * d * d;
        reduce_parts<<<(n + 255) / 256, 256>>>(p_re, p_im, sc_re, sc_im, n, NC);
        softmax_phase<<<BATCH * d, d>>>(sc_re, sc_im, m_re, m_im, d, ltau,
                                        sqrtf((float)SS / (float)d));
        cgemm_nn<<<g1, 256>>>(m_re, m_im, d * d, u_re, u_im, l_re, l_im, d, rest);
        perm_swap01<<<NTOT / 256, 256>>>(l_re, l_im, s_re, s_im);
    }

    // ---------------- Mode 2: d=64, rest=16384 ----------------------------
    {
        const int d = 64, rest = 16384;
        // unfold: u[b, k, p] = s[b, p, k]   (src R=16384, C=64)
        dim3 gt(64 / 32, 16384 / 32, BATCH);
        perm_transpose<<<gt, dim3(32, 8)>>>(s_re, s_im, u_re, u_im, 16384, 64);

        dim3 g1(rest / BN, d / BM, BATCH);
        cgemm_nn<<<g1, 256>>>(w2re, w2im, 0, u_re, u_im, l_re, l_im, d, rest);

        const int NC = 64, KC = rest / NC;        // 256
        dim3 g2(d / BN, d / BM, BATCH * NC);
        cgemm_nt<<<g2, 256>>>(l_re, l_im, u_re, u_im, p_re, p_im, d, rest, KC);

        const int n = BATCH * d * d;
        reduce_parts<<<(n + 255) / 256, 256>>>(p_re, p_im, sc_re, sc_im, n, NC);
        softmax_phase<<<BATCH * d, d>>>(sc_re, sc_im, m_re, m_im, d, ltau,
                                        sqrtf((float)SS / (float)d));
        cgemm_nn<<<g1, 256>>>(m_re, m_im, d * d, u_re, u_im, l_re, l_im, d, rest);

        // fold: out[b, p, k] = mixed[b, k, p]   (src R=64, C=16384) -> d_out
        dim3 gt2(16384 / 32, 64 / 32, BATCH);
        perm_transpose<<<gt2, dim3(32, 8)>>>(l_re, l_im, out_re, out_im, 64, 16384);
    }
}

// round 3
// speedup vs baseline: 1.0997x; 1.0997x over previous
#include <cuda_runtime.h>
#include <math.h>

#define BATCH 8
#define SS 1048576              // 128*128*64
#define NTOT (BATCH * SS)       // 8388608 per component

// ---------------- scratch (device globals; no allocation) ----------------
__device__ float g_s_re[NTOT];
__device__ float g_s_im[NTOT];
__device__ float g_u_re[NTOT];
__device__ float g_u_im[NTOT];
__device__ float g_l_re[NTOT];
__device__ float g_l_im[NTOT];
__device__ float g_p_re[4194304];   // split-K partials (NC*B*d*d max)
__device__ float g_p_im[4194304];
__device__ float g_m_re[131072];    // routing matrix (B*d*d max)
__device__ float g_m_im[131072];

typedef unsigned long long u64;

// ---------------- f32x2 packed-FMA helpers --------------------------------
__device__ __forceinline__ u64 pack2(float x) {
    unsigned xi = __float_as_uint(x);
    u64 r;
    asm("mov.b64 %0, {%1,%2};" : "=l"(r) : "r"(xi), "r"(xi));
    return r;
}
__device__ __forceinline__ void fma2(u64& d, u64 a, u64 b) {
    asm("fma.rn.f32x2 %0, %1, %2, %3;" : "=l"(d) : "l"(a), "l"(b), "l"(d));
}
__device__ __forceinline__ void lds2(u64& lo, u64& hi, const float* p) {
    unsigned a = (unsigned)__cvta_generic_to_shared(p);
    asm volatile("ld.shared.v2.b64 {%0,%1}, [%2];" : "=l"(lo), "=l"(hi) : "r"(a));
}
__device__ __forceinline__ void unpack2(float& lo, float& hi, u64 v) {
    unsigned a, b;
    asm("mov.b64 {%0,%1}, %2;" : "=r"(a), "=r"(b) : "l"(v));
    lo = __uint_as_float(a); hi = __uint_as_float(b);
}

// one Karatsuba-component rank-1 update: T[4][2] += rep(a[0..3]) x b[0..3]
__device__ __forceinline__ void cfrag_fma(u64 T[4][2], const float* ap, const float* bp) {
    float4 av = *(const float4*)ap;
    u64 b0, b1;
    lds2(b0, b1, bp);
    u64 a0 = pack2(av.x), a1 = pack2(av.y), a2 = pack2(av.z), a3 = pack2(av.w);
    fma2(T[0][0], a0, b0); fma2(T[0][1], a0, b1);
    fma2(T[1][0], a1, b0); fma2(T[1][1], a1, b1);
    fma2(T[2][0], a2, b0); fma2(T[2][1], a2, b1);
    fma2(T[3][0], a3, b0); fma2(T[3][1], a3, b1);
}

#define BM 64
#define BN 64
#define BKT 16
#define SPAD 68                 // padded smem row (rows stay 16B-aligned)

// ---------------- complex GEMM NN: C[b] = A(b?) * U[b] --------------------
__global__ __launch_bounds__(256, 2)
void cgemm_nn(const float* __restrict__ Are, const float* __restrict__ Aim, int strideA,
              const float* __restrict__ Ure, const float* __restrict__ Uim,
              float* __restrict__ Cre, float* __restrict__ Cim,
              int d, int rest)
{
    __shared__ __align__(16) float As_re[BKT][SPAD], As_im[BKT][SPAD], As_s[BKT][SPAD];
    __shared__ __align__(16) float Bs_re[BKT][SPAD], Bs_im[BKT][SPAD], Bs_s[BKT][SPAD];

    const int b  = blockIdx.z;
    const int m0 = blockIdx.y * BM;
    const int n0 = blockIdx.x * BN;

    const float* are = Are + (size_t)b * strideA;
    const float* aim = Aim + (size_t)b * strideA;
    const float* ure = Ure + (size_t)b * d * rest;
    const float* uim = Uim + (size_t)b * d * rest;
    float*       cre = Cre + (size_t)b * d * rest;
    float*       cim = Cim + (size_t)b * d * rest;

    const int tid = threadIdx.x;
    const int tn4 = (tid & 15) * 4;
    const int tm4 = (tid >> 4) * 4;
    const int arow = tid >> 2;          // 0..63
    const int ac4  = (tid & 3) * 4;     // 0,4,8,12
    const int ukr  = tid >> 4;          // 0..15
    const int un4  = (tid & 15) * 4;    // 0..60

    u64 T1[4][2], T2[4][2], T3[4][2];
#pragma unroll
    for (int i = 0; i < 4; i++)
#pragma unroll
        for (int p = 0; p < 2; p++) { T1[i][p] = 0ULL; T2[i][p] = 0ULL; T3[i][p] = 0ULL; }

    // prefetch first tile
    float4 pa_r = *(const float4*)(are + (size_t)(m0 + arow) * d + ac4);
    float4 pa_i = *(const float4*)(aim + (size_t)(m0 + arow) * d + ac4);
    float4 pb_r = *(const float4*)(ure + (size_t)ukr * rest + n0 + un4);
    float4 pb_i = *(const float4*)(uim + (size_t)ukr * rest + n0 + un4);

    for (int kk = 0; kk < d; kk += BKT) {
        // store tiles (A transposed, + sum tiles)
        As_re[ac4 + 0][arow] = pa_r.x; As_re[ac4 + 1][arow] = pa_r.y;
        As_re[ac4 + 2][arow] = pa_r.z; As_re[ac4 + 3][arow] = pa_r.w;
        As_im[ac4 + 0][arow] = pa_i.x; As_im[ac4 + 1][arow] = pa_i.y;
        As_im[ac4 + 2][arow] = pa_i.z; As_im[ac4 + 3][arow] = pa_i.w;
        As_s[ac4 + 0][arow] = pa_r.x + pa_i.x; As_s[ac4 + 1][arow] = pa_r.y + pa_i.y;
        As_s[ac4 + 2][arow] = pa_r.z + pa_i.z; As_s[ac4 + 3][arow] = pa_r.w + pa_i.w;
        *(float4*)&Bs_re[ukr][un4] = pb_r;
        *(float4*)&Bs_im[ukr][un4] = pb_i;
        float4 bs = make_float4(pb_r.x + pb_i.x, pb_r.y + pb_i.y,
                                pb_r.z + pb_i.z, pb_r.w + pb_i.w);
        *(float4*)&Bs_s[ukr][un4] = bs;
        __syncthreads();

        if (kk + BKT < d) {     // prefetch next tile (LDGs overlap compute)
            pa_r = *(const float4*)(are + (size_t)(m0 + arow) * d + kk + BKT + ac4);
            pa_i = *(const float4*)(aim + (size_t)(m0 + arow) * d + kk + BKT + ac4);
            pb_r = *(const float4*)(ure + (size_t)(kk + BKT + ukr) * rest + n0 + un4);
            pb_i = *(const float4*)(uim + (size_t)(kk + BKT + ukr) * rest + n0 + un4);
        }

#pragma unroll
        for (int k = 0; k < BKT; k++) {
            cfrag_fma(T1, &As_re[k][tm4], &Bs_re[k][tn4]);
            cfrag_fma(T2, &As_im[k][tm4], &Bs_im[k][tn4]);
            cfrag_fma(T3, &As_s[k][tm4],  &Bs_s[k][tn4]);
        }
        __syncthreads();
    }

#pragma unroll
    for (int i = 0; i < 4; i++) {
        float t1l, t1h, t2l, t2h, t3l, t3h;
        float crv[4], civ[4];
        unpack2(t1l, t1h, T1[i][0]); unpack2(t2l, t2h, T2[i][0]); unpack2(t3l, t3h, T3[i][0]);
        crv[0] = t1l - t2l; crv[1] = t1h - t2h;
        civ[0] = t3l - t1l - t2l; civ[1] = t3h - t1h - t2h;
        unpack2(t1l, t1h, T1[i][1]); unpack2(t2l, t2h, T2[i][1]); unpack2(t3l, t3h, T3[i][1]);
        crv[2] = t1l - t2l; crv[3] = t1h - t2h;
        civ[2] = t3l - t1l - t2l; civ[3] = t3h - t1h - t2h;
        int m = m0 + tm4 + i;
        *(float4*)(cre + (size_t)m * rest + n0 + tn4) = make_float4(crv[0], crv[1], crv[2], crv[3]);
        *(float4*)(cim + (size_t)m * rest + n0 + tn4) = make_float4(civ[0], civ[1], civ[2], civ[3]);
    }
}

// ---------- complex GEMM NT split-K: P[c][b] = L[b] * U[b]^T chunk --------
__global__ __launch_bounds__(256, 2)
void cgemm_nt(const float* __restrict__ Lre, const float* __restrict__ Lim,
              const float* __restrict__ Ure, const float* __restrict__ Uim,
              float* __restrict__ Pre, float* __restrict__ Pim,
              int d, int K, int KC)
{
    __shared__ __align__(16) float As_re[BKT][SPAD], As_im[BKT][SPAD], As_s[BKT][SPAD];
    __shared__ __align__(16) float Bs_re[BKT][SPAD], Bs_im[BKT][SPAD], Bs_s[BKT][SPAD];

    const int bz    = blockIdx.z;
    const int b     = bz & 7;
    const int chunk = bz >> 3;
    const int m0    = blockIdx.y * BM;
    const int n0    = blockIdx.x * BN;

    const float* lre = Lre + (size_t)b * d * K;
    const float* lim = Lim + (size_t)b * d * K;
    const float* ure = Ure + (size_t)b * d * K;
    const float* uim = Uim + (size_t)b * d * K;

    const int tid = threadIdx.x;
    const int tn4 = (tid & 15) * 4;
    const int tm4 = (tid >> 4) * 4;
    const int arow = tid >> 2;
    const int ac4  = (tid & 3) * 4;

    u64 T1[4][2], T2[4][2], T3[4][2];
#pragma unroll
    for (int i = 0; i < 4; i++)
#pragma unroll
        for (int p = 0; p < 2; p++) { T1[i][p] = 0ULL; T2[i][p] = 0ULL; T3[i][p] = 0ULL; }

    const int kbeg = chunk * KC;
    const int kend = kbeg + KC;

    float4 pa_r = *(const float4*)(lre + (size_t)(m0 + arow) * K + kbeg + ac4);
    float4 pa_i = *(const float4*)(lim + (size_t)(m0 + arow) * K + kbeg + ac4);
    float4 pb_r = *(const float4*)(ure + (size_t)(n0 + arow) * K + kbeg + ac4);
    float4 pb_i = *(const float4*)(uim + (size_t)(n0 + arow) * K + kbeg + ac4);

    for (int kk = kbeg; kk < kend; kk += BKT) {
        As_re[ac4 + 0][arow] = pa_r.x; As_re[ac4 + 1][arow] = pa_r.y;
        As_re[ac4 + 2][arow] = pa_r.z; As_re[ac4 + 3][arow] = pa_r.w;
        As_im[ac4 + 0][arow] = pa_i.x; As_im[ac4 + 1][arow] = pa_i.y;
        As_im[ac4 + 2][arow] = pa_i.z; As_im[ac4 + 3][arow] = pa_i.w;
        As_s[ac4 + 0][arow] = pa_r.x + pa_i.x; As_s[ac4 + 1][arow] = pa_r.y + pa_i.y;
        As_s[ac4 + 2][arow] = pa_r.z + pa_i.z; As_s[ac4 + 3][arow] = pa_r.w + pa_i.w;
        Bs_re[ac4 + 0][arow] = pb_r.x; Bs_re[ac4 + 1][arow] = pb_r.y;
        Bs_re[ac4 + 2][arow] = pb_r.z; Bs_re[ac4 + 3][arow] = pb_r.w;
        Bs_im[ac4 + 0][arow] = pb_i.x; Bs_im[ac4 + 1][arow] = pb_i.y;
        Bs_im[ac4 + 2][arow] = pb_i.z; Bs_im[ac4 + 3][arow] = pb_i.w;
        Bs_s[ac4 + 0][arow] = pb_r.x + pb_i.x; Bs_s[ac4 + 1][arow] = pb_r.y + pb_i.y;
        Bs_s[ac4 + 2][arow] = pb_r.z + pb_i.z; Bs_s[ac4 + 3][arow] = pb_r.w + pb_i.w;
        __syncthreads();

        if (kk + BKT < kend) {
            pa_r = *(const float4*)(lre + (size_t)(m0 + arow) * K + kk + BKT + ac4);
            pa_i = *(const float4*)(lim + (size_t)(m0 + arow) * K + kk + BKT + ac4);
            pb_r = *(const float4*)(ure + (size_t)(n0 + arow) * K + kk + BKT + ac4);
            pb_i = *(const float4*)(uim + (size_t)(n0 + arow) * K + kk + BKT + ac4);
        }

#pragma unroll
        for (int k = 0; k < BKT; k++) {
            cfrag_fma(T1, &As_re[k][tm4], &Bs_re[k][tn4]);
            cfrag_fma(T2, &As_im[k][tm4], &Bs_im[k][tn4]);
            cfrag_fma(T3, &As_s[k][tm4],  &Bs_s[k][tn4]);
        }
        __syncthreads();
    }

    size_t off = (size_t)(chunk * BATCH + b) * d * d;
#pragma unroll
    for (int i = 0; i < 4; i++) {
        float t1l, t1h, t2l, t2h, t3l, t3h;
        float crv[4], civ[4];
        unpack2(t1l, t1h, T1[i][0]); unpack2(t2l, t2h, T2[i][0]); unpack2(t3l, t3h, T3[i][0]);
        crv[0] = t1l - t2l; crv[1] = t1h - t2h;
        civ[0] = t3l - t1l - t2l; civ[1] = t3h - t1h - t2h;
        unpack2(t1l, t1h, T1[i][1]); unpack2(t2l, t2h, T2[i][1]); unpack2(t3l, t3h, T3[i][1]);
        crv[2] = t1l - t2l; crv[3] = t1h - t2h;
        civ[2] = t3l - t1l - t2l; civ[3] = t3h - t1h - t2h;
        int m = m0 + tm4 + i;
        *(float4*)(Pre + off + (size_t)m * d + n0 + tn4) = make_float4(crv[0], crv[1], crv[2], crv[3]);
        *(float4*)(Pim + off + (size_t)m * d + n0 + tn4) = make_float4(civ[0], civ[1], civ[2], civ[3]);
    }
}

// ---------------- fused split-K reduce + softmax(|s|/scale)*phase ---------
__global__ void softmax_fused(const float* __restrict__ Pre, const float* __restrict__ Pim,
                              float* __restrict__ Mre, float* __restrict__ Mim,
                              int d, int n, int nchunks,
                              const float* __restrict__ logtau, float sfac)
{
    const int row = blockIdx.x;
    const int j   = threadIdx.x;
    const int idx = row * d + j;

    float sr = 0.f, si = 0.f;
    for (int c = 0; c < nchunks; c++) {
        sr += Pre[(size_t)c * n + idx];
        si += Pim[(size_t)c * n + idx];
    }
    const float mag = sqrtf(sr * sr + si * si);

    const float tau   = fmaxf(expf(logtau[0]), 1e-8f);
    const float scale = tau * sfac;
    const float logit = mag / scale;

    __shared__ float wred[4];
    __shared__ float wsum[4];
    const int warp = j >> 5, lane = j & 31, nw = d >> 5;

    float v = logit;
#pragma unroll
    for (int o = 16; o > 0; o >>= 1) v = fmaxf(v, __shfl_xor_sync(0xffffffffu, v, o));
    if (lane == 0) wred[warp] = v;
    __syncthreads();
    float mx = wred[0];
    for (int w = 1; w < nw; w++) mx = fmaxf(mx, wred[w]);

    const float e = expf(logit - mx);
    float s_ = e;
#pragma unroll
    for (int o = 16; o > 0; o >>= 1) s_ += __shfl_xor_sync(0xffffffffu, s_, o);
    if (lane == 0) wsum[warp] = s_;
    __syncthreads();
    float tot = 0.f;
    for (int w = 0; w < nw; w++) tot += wsum[w];

    const float routing = e / tot;
    float pr, pi;
    if (mag > 1e-8f) { pr = sr / mag; pi = si / mag; }
    else             { pr = 1.f;      pi = 0.f; }
    Mre[(size_t)row * d + j] = routing * pr;
    Mim[(size_t)row * d + j] = routing * pi;
}

// ---------------- mode-1 permute (float4): swap the two 128-axes ----------
__global__ void perm_swap01(const float4* __restrict__ s4re, const float4* __restrict__ s4im,
                            float4* __restrict__ d4re, float4* __restrict__ d4im)
{
    int t = blockIdx.x * 256 + threadIdx.x;     // < NTOT/4 = 2097152
    int k4 = t & 15;
    int q  = (t >> 4) & 127;
    int p  = (t >> 11) & 127;
    int b  = t >> 18;
    int src = ((((b << 7) | q) << 7) | p) << 4 | k4;
    d4re[t] = s4re[src];
    d4im[t] = s4im[src];
}

// ---------------- batched 2D transpose: dst[b][c][r] = src[b][r][c] -------
__global__ void perm_transpose(const float* __restrict__ sre, const float* __restrict__ sim,
                               float* __restrict__ dre, float* __restrict__ dim_,
                               int R, int C)
{
    __shared__ float tre[32][33], tim[32][33];
    const int b  = blockIdx.z;
    const int r0 = blockIdx.y * 32;
    const int c0 = blockIdx.x * 32;
    const float* sr_ = sre + (size_t)b * R * C;
    const float* si_ = sim + (size_t)b * R * C;
    float*       dr_ = dre + (size_t)b * R * C;
    float*       di_ = dim_ + (size_t)b * R * C;
    const int x = threadIdx.x, y = threadIdx.y;    // 32 x 8
#pragma unroll
    for (int i = y; i < 32; i += 8) {
        tre[i][x] = sr_[(size_t)(r0 + i) * C + c0 + x];
        tim[i][x] = si_[(size_t)(r0 + i) * C + c0 + x];
    }
    __syncthreads();
#pragma unroll
    for (int i = y; i < 32; i += 8) {
        dr_[(size_t)(c0 + i) * R + r0 + x] = tre[x][i];
        di_[(size_t)(c0 + i) * R + r0 + x] = tim[x][i];
    }
}

// --------------------------------------------------------------------------
extern "C" void kernel_launch(void* const* d_in, const int* in_sizes, int n_in,
                              void* d_out, int out_size)
{
    (void)in_sizes; (void)n_in; (void)out_size;
    const float* xre  = (const float*)d_in[0];
    const float* xim  = (const float*)d_in[1];
    const float* w0re = (const float*)d_in[2];
    const float* w0im = (const float*)d_in[3];
    const float* w1re = (const float*)d_in[4];
    const float* w1im = (const float*)d_in[5];
    const float* w2re = (const float*)d_in[6];
    const float* w2im = (const float*)d_in[7];
    const float* ltau = (const float*)d_in[8];
    float* out_re = (float*)d_out;
    float* out_im = out_re + (size_t)NTOT;

    float *s_re, *s_im, *u_re, *u_im, *l_re, *l_im, *p_re, *p_im, *m_re, *m_im;
    cudaGetSymbolAddress((void**)&s_re,  g_s_re);
    cudaGetSymbolAddress((void**)&s_im,  g_s_im);
    cudaGetSymbolAddress((void**)&u_re,  g_u_re);
    cudaGetSymbolAddress((void**)&u_im,  g_u_im);
    cudaGetSymbolAddress((void**)&l_re,  g_l_re);
    cudaGetSymbolAddress((void**)&l_im,  g_l_im);
    cudaGetSymbolAddress((void**)&p_re,  g_p_re);
    cudaGetSymbolAddress((void**)&p_im,  g_p_im);
    cudaGetSymbolAddress((void**)&m_re,  g_m_re);
    cudaGetSymbolAddress((void**)&m_im,  g_m_im);

    // ---------------- Mode 0: d=128, rest=8192 (unfold = identity) --------
    {
        const int d = 128, rest = 8192;
        dim3 g1(rest / BN, d / BM, BATCH);
        cgemm_nn<<<g1, 256>>>(w0re, w0im, 0, xre, xim, l_re, l_im, d, rest);

        const int NC = 32, KC = rest / NC;        // 256
        dim3 g2(d / BN, d / BM, BATCH * NC);
        cgemm_nt<<<g2, 256>>>(l_re, l_im, xre, xim, p_re, p_im, d, rest, KC);

        const int n = BATCH * d * d;
        softmax_fused<<<BATCH * d, d>>>(p_re, p_im, m_re, m_im, d, n, NC, ltau,
                                        sqrtf((float)SS / (float)d));
        cgemm_nn<<<g1, 256>>>(m_re, m_im, d * d, xre, xim, s_re, s_im, d, rest);
    }

    // ---------------- Mode 1: d=128, rest=8192 ----------------------------
    {
        const int d = 128, rest = 8192;
        perm_swap01<<<(NTOT / 4) / 256, 256>>>((const float4*)s_re, (const float4*)s_im,
                                               (float4*)u_re, (float4*)u_im);

        dim3 g1(rest / BN, d / BM, BATCH);
        cgemm_nn<<<g1, 256>>>(w1re, w1im, 0, u_re, u_im, l_re, l_im, d, rest);

        const int NC = 32, KC = rest / NC;
        dim3 g2(d / BN, d / BM, BATCH * NC);
        cgemm_nt<<<g2, 256>>>(l_re, l_im, u_re, u_im, p_re, p_im, d, rest, KC);

        const int n = BATCH * d * d;
        softmax_fused<<<BATCH * d, d>>>(p_re, p_im, m_re, m_im, d, n, NC, ltau,
                                        sqrtf((float)SS / (float)d));
        cgemm_nn<<<g1, 256>>>(m_re, m_im, d * d, u_re, u_im, l_re, l_im, d, rest);
        perm_swap01<<<(NTOT / 4) / 256, 256>>>((const float4*)l_re, (const float4*)l_im,
                                               (float4*)s_re, (float4*)s_im);
    }

    // ---------------- Mode 2: d=64, rest=16384 ----------------------------
    {
        const int d = 64, rest = 16384;
        // unfold: u[b, k, p] = s[b, p, k]   (src R=16384, C=64)
        dim3 gt(64 / 32, 16384 / 32, BATCH);
        perm_transpose<<<gt, dim3(32, 8)>>>(s_re, s_im, u_re, u_im, 16384, 64);

        dim3 g1(rest / BN, d / BM, BATCH);
        cgemm_nn<<<g1, 256>>>(w2re, w2im, 0, u_re, u_im, l_re, l_im, d, rest);

        const int NC = 64, KC = rest / NC;        // 256
        dim3 g2(d / BN, d / BM, BATCH * NC);
        cgemm_nt<<<g2, 256>>>(l_re, l_im, u_re, u_im, p_re, p_im, d, rest, KC);

        const int n = BATCH * d * d;
        softmax_fused<<<BATCH * d, d>>>(p_re, p_im, m_re, m_im, d, n, NC, ltau,
                                        sqrtf((float)SS / (float)d));
        cgemm_nn<<<g1, 256>>>(m_re, m_im, d * d, u_re, u_im, l_re, l_im, d, rest);

        // fold: out[b, p, k] = mixed[b, k, p]   (src R=64, C=16384) -> d_out
        dim3 gt2(16384 / 32, 64 / 32, BATCH);
        perm_transpose<<<gt2, dim3(32, 8)>>>(l_re, l_im, out_re, out_im, 64, 16384);
    }
}